// round 4
// baseline (speedup 1.0000x reference)
#include <cuda_runtime.h>
#include <math_constants.h>

#define TPB   256
#define MI    2048                     // interpolation cells
#define TABN  (MI + 2)                 // float2 table entries: j in [0, MI+1]
#define KMAX  1024
#define LOF   (-0.015625f)             // table domain start
#define HSTEP (33.0f/65536.0f)         // cell width h (exact in fp32)
#define INVH  (65536.0f/33.0f)         // 1/h
#define TT0   (1024.0f/33.0f)          // -LOF/h

// Device scratch (no allocations allowed)
__device__ float4 g_params[KMAX];      // {mu, s=-0.5*inv_var*log2e, b=log2(coef), 0}
__device__ float2 g_tab2[TABN];        // overlapped: tab2[j] = {y[j-1], y[j]}
__device__ int    g_interp;            // 1 -> interpolation valid
__device__ float  g_mx, g_tot;         // softmax stats (K>KMAX ultra-fallback)

__device__ __forceinline__ float ex2(float a) {
    float r;
    asm("ex2.approx.f32 %0, %1;" : "=f"(r) : "f"(a));
    return r;
}

// ---------------------------------------------------------------------------
// Builder: softmax + param fold (redundantly per block), then each thread
// evaluates ONE table grid point exactly (full K sum) and scatters it into the
// 2 overlapped float2 slots referencing it. Block 0 publishes params/flags.
// ---------------------------------------------------------------------------
__global__ void build_kernel(const float* __restrict__ pi_l,
                             const float* __restrict__ mu,
                             const float* __restrict__ lv, int K) {
    __shared__ float  sred[TPB];
    __shared__ float4 sp[KMAX];        // 16 KB
    int t = threadIdx.x;
    int kok = (K <= KMAX);

    // softmax max
    float m = -CUDART_INF_F;
    for (int k = t; k < K; k += TPB) m = fmaxf(m, pi_l[k]);
    sred[t] = m; __syncthreads();
    for (int s = TPB / 2; s > 0; s >>= 1) {
        if (t < s) sred[t] = fmaxf(sred[t], sred[t + s]);
        __syncthreads();
    }
    float mx = sred[0]; __syncthreads();

    // softmax sum
    float sum = 0.f;
    for (int k = t; k < K; k += TPB) sum += expf(pi_l[k] - mx);
    sred[t] = sum; __syncthreads();
    for (int s = TPB / 2; s > 0; s >>= 1) {
        if (t < s) sred[t] += sred[t + s];
        __syncthreads();
    }
    float tot = sred[0]; __syncthreads();

    // params + min sigma
    float smin = CUDART_INF_F;
    if (kok) {
        for (int k = t; k < K; k += TPB) {
            float pi   = expf(pi_l[k] - mx) / tot;
            float l    = lv[k];
            float sig  = expf(0.5f * l);
            smin = fminf(smin, sig);
            float coef = pi * 0.39894228040143267794f * expf(-0.5f * l);
            float s2   = -0.5f * expf(-l) * 1.44269504088896340736f;
            float b    = log2f(fmaxf(coef, 1e-38f));
            sp[k] = make_float4(mu[k], s2, b, 0.f);
        }
    }
    sred[t] = smin; __syncthreads();
    for (int s = TPB / 2; s > 0; s >>= 1) {
        if (t < s) sred[t] = fminf(sred[t], sred[t + s]);
        __syncthreads();
    }
    smin = sred[0];
    __syncthreads();

    if (blockIdx.x == 0) {
        if (kok) for (int k = t; k < K; k += TPB) g_params[k] = sp[k];
        if (t == 0) {
            g_interp = (kok && smin >= 6.0f * HSTEP) ? 1 : 0;
            g_mx = mx; g_tot = tot;
        }
    }
    if (!kok) return;

    // Evaluate table grid point p = gt - 1, p in [-1, MI+1]
    int gt = blockIdx.x * TPB + t;
    if (gt > MI + 2) return;
    int p = gt - 1;
    float x = LOF + (float)p * HSTEP;
    float acc = 0.f;
    for (int k = 0; k < K; k++) {
        float4 pp = sp[k];
        float d = x - pp.x;
        acc += ex2(fmaf(d * d, pp.y, pp.z));
    }
    // scatter: tab2[j] = {y[j-1], y[j]}
    if (p + 1 <= MI + 1)            ((float*)&g_tab2[p + 1])[0] = acc;
    if (p >= 0 && p <= MI + 1)      ((float*)&g_tab2[p])[1]     = acc;
}

// ---------------------------------------------------------------------------
// Fallback direct evaluations (cold paths)
// ---------------------------------------------------------------------------
__device__ __noinline__ float direct_eval(float x, int K) {
    float acc = 0.f;
    for (int k = 0; k < K; k++) {
        float4 p = g_params[k];
        float d = x - p.x;
        acc += ex2(fmaf(d * d, p.y, p.z));
    }
    return acc;
}

__device__ __noinline__ float direct_eval_raw(float x, const float* pi_l,
                                              const float* mu, const float* lv, int K) {
    float mx = g_mx, tot = g_tot;
    float acc = 0.f;
    for (int k = 0; k < K; k++) {
        float pi   = expf(pi_l[k] - mx) / tot;
        float l    = lv[k];
        float coef = pi * 0.39894228040143267794f * expf(-0.5f * l);
        float d    = x - mu[k];
        acc += coef * expf(-0.5f * d * d * expf(-l));
    }
    return acc;
}

// ---------------------------------------------------------------------------
// Cubic (4-pt Lagrange) interpolation from the smem float2 table.
// Index clamped: exact for x in [LOF, LOF + MI*h] which covers [0,1].
// ---------------------------------------------------------------------------
__device__ __forceinline__ float interp1(float x, const float2* __restrict__ stab) {
    float t = fmaf(x, INVH, TT0);
    int i = __float2int_rz(t);
    i = min(max(i, 0), MI - 1);
    float f = t - (float)i;
    float2 lo = stab[i];       // {y[i-1], y[i]}
    float2 hi = stab[i + 2];   // {y[i+1], y[i+2]}
    float fm1 = f - 1.f, fm2 = f - 2.f, fp1 = f + 1.f;
    float a = f * fm1;
    float b = fp1 * fm2;
    float w0 = -0.166666667f * a * fm2;
    float w1 =  0.5f * fm1 * b;
    float w2 = -0.5f * f * b;
    float w3 =  0.166666667f * a * fp1;
    return fmaf(w0, lo.x, fmaf(w1, lo.y, fmaf(w2, hi.x, w3 * hi.y)));
}

__global__ __launch_bounds__(TPB, 8)
void interp_kernel(const float* __restrict__ mz,
                   float* __restrict__ out,
                   int n, int K,
                   const float* __restrict__ pi_l,
                   const float* __restrict__ mu,
                   const float* __restrict__ lv) {
    __shared__ float2 stab[TABN];        // ~16 KB
    int mode = g_interp;                 // uniform across grid
    if (mode) {
        for (int i = threadIdx.x; i < TABN; i += TPB)
            stab[i] = g_tab2[i];
    }
    __syncthreads();

    int gtid = blockIdx.x * TPB + threadIdx.x;
    int gsz  = gridDim.x * TPB;

    if (mode) {
        int n4 = n >> 2;
        const float4* mz4 = (const float4*)mz;
        float4* out4 = (float4*)out;
        for (int i = gtid; i < n4; i += gsz) {
            float4 z = mz4[i];
            float4 r;
            r.x = interp1(z.x, stab);
            r.y = interp1(z.y, stab);
            r.z = interp1(z.z, stab);
            r.w = interp1(z.w, stab);
            out4[i] = r;
        }
        int rem = n & 3;
        if (gtid < rem) {
            int i = (n4 << 2) + gtid;
            out[i] = interp1(mz[i], stab);
        }
    } else if (K <= KMAX) {
        for (int i = gtid; i < n; i += gsz)
            out[i] = direct_eval(mz[i], K);
    } else {
        for (int i = gtid; i < n; i += gsz)
            out[i] = direct_eval_raw(mz[i], pi_l, mu, lv, K);
    }
}

// ---------------------------------------------------------------------------
// Inputs (metadata order): mz [N], pi_l [K], mu [K], lv [K]. Output: prob [N] f32.
// ---------------------------------------------------------------------------
extern "C" void kernel_launch(void* const* d_in, const int* in_sizes, int n_in,
                              void* d_out, int out_size) {
    const float* mz   = (const float*)d_in[0];
    const float* pi_l = (const float*)d_in[1];
    const float* mu   = (const float*)d_in[2];
    const float* lv   = (const float*)d_in[3];
    float* out = (float*)d_out;
    int n = in_sizes[0];
    int K = in_sizes[1];

    int blocks_b = (MI + 3 + TPB - 1) / TPB;   // 9
    build_kernel<<<blocks_b, TPB>>>(pi_l, mu, lv, K);

    int blocks = 148 * 8;                       // one full occupancy wave
    int need = (n / 4 + TPB - 1) / TPB;
    if (need < 1) need = 1;
    if (blocks > need) blocks = need;
    interp_kernel<<<blocks, TPB>>>(mz, out, n, K, pi_l, mu, lv);
}